// round 4
// baseline (speedup 1.0000x reference)
#include <cuda_runtime.h>
#include <math.h>

// Problem dims (LinearAttnBlock: B=8, C=256, H=W=64)
#define BATCH 8
#define CDIM  256
#define NDIM  4096
#define GRP   32
#define SPLITS 16

// Scratch (no allocation allowed -> __device__ globals)
__device__ float  g_qkv[(size_t)BATCH * 3 * CDIM * NDIM];  // [b][q/k/v][c][n]
__device__ float  g_kv [BATCH * CDIM * CDIM];              // [b][c][d]
__device__ float  g_M  [BATCH * CDIM * CDIM];              // [b][o][c]
__device__ float2 g_stats[BATCH * GRP];                    // (mean, rstd)

// ---------------------------------------------------------------------------
// K1: GroupNorm statistics. One block per (b, g); group data is contiguous
// (8 channels x 4096 = 32768 floats).
// ---------------------------------------------------------------------------
__global__ __launch_bounds__(256) void k_stats(const float* __restrict__ x) {
    const int bg = blockIdx.x;
    const float4* p = reinterpret_cast<const float4*>(x + (size_t)bg * 8 * NDIM);
    float s = 0.f, s2 = 0.f;
    for (int i = threadIdx.x; i < 8 * NDIM / 4; i += 256) {
        float4 v = p[i];
        s  += v.x + v.y + v.z + v.w;
        s2 += v.x * v.x + v.y * v.y + v.z * v.z + v.w * v.w;
    }
    __shared__ float sh0[8], sh1[8];
    #pragma unroll
    for (int o = 16; o > 0; o >>= 1) {
        s  += __shfl_down_sync(0xffffffffu, s,  o);
        s2 += __shfl_down_sync(0xffffffffu, s2, o);
    }
    const int lane = threadIdx.x & 31, w = threadIdx.x >> 5;
    if (lane == 0) { sh0[w] = s; sh1[w] = s2; }
    __syncthreads();
    if (w == 0) {
        s  = (lane < 8) ? sh0[lane] : 0.f;
        s2 = (lane < 8) ? sh1[lane] : 0.f;
        #pragma unroll
        for (int o = 4; o > 0; o >>= 1) {
            s  += __shfl_down_sync(0xffffffffu, s,  o);
            s2 += __shfl_down_sync(0xffffffffu, s2, o);
        }
        if (lane == 0) {
            const float inv = 1.f / (8.f * NDIM);
            float mean = s * inv;
            float var  = s2 * inv - mean * mean;
            g_stats[bg] = make_float2(mean, rsqrtf(var + 1e-6f));
        }
    }
}

// ---------------------------------------------------------------------------
// K2: QKV = W_{q,k,v} @ GN(x).  M=768 (stacked), N=4096, K=256 per batch.
// GroupNorm folded into B-operand load; bias + (elu+1) in epilogue.
// 128x128x8 tile, 8x8 per thread, 256 threads.
// ---------------------------------------------------------------------------
__global__ __launch_bounds__(256) void k_qkv(
    const float* __restrict__ x,
    const float* __restrict__ wq, const float* __restrict__ bq,
    const float* __restrict__ wk, const float* __restrict__ bk,
    const float* __restrict__ wv, const float* __restrict__ bv,
    const float* __restrict__ gamma, const float* __restrict__ beta)
{
    const int b  = blockIdx.z;
    const int by = blockIdx.y;            // 0..5
    const int n0 = blockIdx.x * 128;
    const int which = by >> 1;            // 0=q 1=k 2=v
    const int m0 = (by & 1) * 128;
    const float* W    = which == 0 ? wq : which == 1 ? wk : wv;
    const float* bias = which == 0 ? bq : which == 1 ? bk : bv;

    __shared__ float As[8][128];
    __shared__ float Bs[8][128];

    const int tid  = threadIdx.x;
    const int arow = tid >> 1, acol = (tid & 1) << 2;
    const int brow = tid >> 5, bcol = (tid & 31) << 2;
    const int tx = (tid & 15) << 3, ty = (tid >> 4) << 3;

    const float*  xb = x + (size_t)b * CDIM * NDIM;
    const float2* st = g_stats + b * GRP;

    float acc[8][8];
    #pragma unroll
    for (int i = 0; i < 8; i++)
        #pragma unroll
        for (int j = 0; j < 8; j++) acc[i][j] = 0.f;

    for (int k0 = 0; k0 < CDIM; k0 += 8) {
        float4 av = *reinterpret_cast<const float4*>(W + (m0 + arow) * CDIM + k0 + acol);
        As[acol + 0][arow] = av.x;
        As[acol + 1][arow] = av.y;
        As[acol + 2][arow] = av.z;
        As[acol + 3][arow] = av.w;

        const int c = k0 + brow;
        float2 ms = st[c >> 3];
        float scale = ms.y * gamma[c];
        float shift = fmaf(-ms.x, scale, beta[c]);
        float4 xv = *reinterpret_cast<const float4*>(xb + (size_t)c * NDIM + n0 + bcol);
        *reinterpret_cast<float4*>(&Bs[brow][bcol]) =
            make_float4(fmaf(xv.x, scale, shift), fmaf(xv.y, scale, shift),
                        fmaf(xv.z, scale, shift), fmaf(xv.w, scale, shift));
        __syncthreads();
        #pragma unroll
        for (int k = 0; k < 8; k++) {
            float4 a0 = *reinterpret_cast<const float4*>(&As[k][ty]);
            float4 a1 = *reinterpret_cast<const float4*>(&As[k][ty + 4]);
            float4 b0 = *reinterpret_cast<const float4*>(&Bs[k][tx]);
            float4 b1 = *reinterpret_cast<const float4*>(&Bs[k][tx + 4]);
            float a[8] = {a0.x, a0.y, a0.z, a0.w, a1.x, a1.y, a1.z, a1.w};
            float bb[8] = {b0.x, b0.y, b0.z, b0.w, b1.x, b1.y, b1.z, b1.w};
            #pragma unroll
            for (int i = 0; i < 8; i++)
                #pragma unroll
                for (int j = 0; j < 8; j++)
                    acc[i][j] = fmaf(a[i], bb[j], acc[i][j]);
        }
        __syncthreads();
    }

    float* outb = g_qkv + (((size_t)b * 3 + which) * CDIM + m0) * NDIM;
    const bool act = (which < 2);
    #pragma unroll
    for (int i = 0; i < 8; i++) {
        const int row = ty + i;
        const float bi = bias[m0 + row];
        float v[8];
        #pragma unroll
        for (int j = 0; j < 8; j++) {
            float t = acc[i][j] + bi;
            if (act) t = (t > 0.f) ? (t + 1.f) : expf(t);   // elu(t)+1
            v[j] = t;
        }
        float* orow = outb + (size_t)row * NDIM + n0 + tx;
        *reinterpret_cast<float4*>(orow)     = make_float4(v[0], v[1], v[2], v[3]);
        *reinterpret_cast<float4*>(orow + 4) = make_float4(v[4], v[5], v[6], v[7]);
    }
}

// ---------------------------------------------------------------------------
// zero g_kv (needed every replay; graph replays reuse scratch)
// ---------------------------------------------------------------------------
__global__ void k_zero() {
    reinterpret_cast<float4*>(g_kv)[blockIdx.x * 256 + threadIdx.x] =
        make_float4(0.f, 0.f, 0.f, 0.f);
}

// ---------------------------------------------------------------------------
// K3: kv[b][c][d] = sum_n K[c,n] V[d,n].  Split-K over n (16 splits),
// atomicAdd epilogue. 128x128x8 tiles.
// ---------------------------------------------------------------------------
__global__ __launch_bounds__(256) void k_kvmat() {
    const int zb = blockIdx.z;
    const int b = zb >> 4, s = zb & 15;
    const int c0 = blockIdx.y * 128, d0 = blockIdx.x * 128;
    const int nb = s * (NDIM / SPLITS);
    const float* Kf = g_qkv + ((size_t)b * 3 + 1) * CDIM * NDIM;
    const float* Vf = g_qkv + ((size_t)b * 3 + 2) * CDIM * NDIM;

    __shared__ float As[8][128];
    __shared__ float Bs[8][128];
    const int tid  = threadIdx.x;
    const int arow = tid >> 1, acol = (tid & 1) << 2;
    const int tx = (tid & 15) << 3, ty = (tid >> 4) << 3;

    float acc[8][8];
    #pragma unroll
    for (int i = 0; i < 8; i++)
        #pragma unroll
        for (int j = 0; j < 8; j++) acc[i][j] = 0.f;

    for (int k0 = 0; k0 < NDIM / SPLITS; k0 += 8) {
        float4 av = *reinterpret_cast<const float4*>(Kf + (size_t)(c0 + arow) * NDIM + nb + k0 + acol);
        As[acol + 0][arow] = av.x; As[acol + 1][arow] = av.y;
        As[acol + 2][arow] = av.z; As[acol + 3][arow] = av.w;
        float4 bv = *reinterpret_cast<const float4*>(Vf + (size_t)(d0 + arow) * NDIM + nb + k0 + acol);
        Bs[acol + 0][arow] = bv.x; Bs[acol + 1][arow] = bv.y;
        Bs[acol + 2][arow] = bv.z; Bs[acol + 3][arow] = bv.w;
        __syncthreads();
        #pragma unroll
        for (int k = 0; k < 8; k++) {
            float4 a0 = *reinterpret_cast<const float4*>(&As[k][ty]);
            float4 a1 = *reinterpret_cast<const float4*>(&As[k][ty + 4]);
            float4 b0 = *reinterpret_cast<const float4*>(&Bs[k][tx]);
            float4 b1 = *reinterpret_cast<const float4*>(&Bs[k][tx + 4]);
            float a[8] = {a0.x, a0.y, a0.z, a0.w, a1.x, a1.y, a1.z, a1.w};
            float bb[8] = {b0.x, b0.y, b0.z, b0.w, b1.x, b1.y, b1.z, b1.w};
            #pragma unroll
            for (int i = 0; i < 8; i++)
                #pragma unroll
                for (int j = 0; j < 8; j++)
                    acc[i][j] = fmaf(a[i], bb[j], acc[i][j]);
        }
        __syncthreads();
    }
    float* kvb = g_kv + b * CDIM * CDIM;
    #pragma unroll
    for (int i = 0; i < 8; i++) {
        float* row = kvb + (c0 + ty + i) * CDIM + d0 + tx;
        #pragma unroll
        for (int j = 0; j < 8; j++) atomicAdd(row + j, acc[i][j]);
    }
}

// ---------------------------------------------------------------------------
// K4: M[b][o][c] = sum_d wo[o,d] * kv[b][c][d].  Tiny 256^3 GEMM per batch.
// 64x64x16 tiles, 4x4 per thread.
// ---------------------------------------------------------------------------
__global__ __launch_bounds__(256) void k_wokv(const float* __restrict__ wo) {
    const int b  = blockIdx.z;
    const int o0 = blockIdx.y * 64, c0 = blockIdx.x * 64;
    const float* kvb = g_kv + b * CDIM * CDIM;

    __shared__ float As[16][64];
    __shared__ float Bs[16][64];
    const int tid  = threadIdx.x;
    const int arow = tid >> 2, acol = (tid & 3) << 2;
    const int tx = (tid & 15) << 2, ty = (tid >> 4) << 2;

    float acc[4][4];
    #pragma unroll
    for (int i = 0; i < 4; i++)
        #pragma unroll
        for (int j = 0; j < 4; j++) acc[i][j] = 0.f;

    for (int k0 = 0; k0 < CDIM; k0 += 16) {
        float4 av = *reinterpret_cast<const float4*>(wo + (o0 + arow) * CDIM + k0 + acol);
        As[acol + 0][arow] = av.x; As[acol + 1][arow] = av.y;
        As[acol + 2][arow] = av.z; As[acol + 3][arow] = av.w;
        float4 bv = *reinterpret_cast<const float4*>(kvb + (c0 + arow) * CDIM + k0 + acol);
        Bs[acol + 0][arow] = bv.x; Bs[acol + 1][arow] = bv.y;
        Bs[acol + 2][arow] = bv.z; Bs[acol + 3][arow] = bv.w;
        __syncthreads();
        #pragma unroll
        for (int k = 0; k < 16; k++) {
            float4 a4 = *reinterpret_cast<const float4*>(&As[k][ty]);
            float4 b4 = *reinterpret_cast<const float4*>(&Bs[k][tx]);
            float a[4] = {a4.x, a4.y, a4.z, a4.w};
            float bb[4] = {b4.x, b4.y, b4.z, b4.w};
            #pragma unroll
            for (int i = 0; i < 4; i++)
                #pragma unroll
                for (int j = 0; j < 4; j++)
                    acc[i][j] = fmaf(a[i], bb[j], acc[i][j]);
        }
        __syncthreads();
    }
    float* Mb = g_M + b * CDIM * CDIM;
    #pragma unroll
    for (int i = 0; i < 4; i++)
        *reinterpret_cast<float4*>(Mb + (o0 + ty + i) * CDIM + c0 + tx) =
            make_float4(acc[i][0], acc[i][1], acc[i][2], acc[i][3]);
}

// ---------------------------------------------------------------------------
// K5: out[b][o][n] = x[b][o][n] + sum_c M[b][o][c] * Q[b][c][n] + bo[o]
// 128x128x8 tiles.
// ---------------------------------------------------------------------------
__global__ __launch_bounds__(256) void k_out(const float* __restrict__ x,
                                             const float* __restrict__ bo,
                                             float* __restrict__ out) {
    const int b  = blockIdx.z;
    const int o0 = blockIdx.y * 128, n0 = blockIdx.x * 128;
    const float* Mb = g_M + b * CDIM * CDIM;
    const float* Qf = g_qkv + (size_t)b * 3 * CDIM * NDIM;

    __shared__ float As[8][128];
    __shared__ float Bs[8][128];
    const int tid  = threadIdx.x;
    const int arow = tid >> 1, acol = (tid & 1) << 2;
    const int brow = tid >> 5, bcol = (tid & 31) << 2;
    const int tx = (tid & 15) << 3, ty = (tid >> 4) << 3;

    float acc[8][8];
    #pragma unroll
    for (int i = 0; i < 8; i++)
        #pragma unroll
        for (int j = 0; j < 8; j++) acc[i][j] = 0.f;

    for (int k0 = 0; k0 < CDIM; k0 += 8) {
        float4 av = *reinterpret_cast<const float4*>(Mb + (o0 + arow) * CDIM + k0 + acol);
        As[acol + 0][arow] = av.x; As[acol + 1][arow] = av.y;
        As[acol + 2][arow] = av.z; As[acol + 3][arow] = av.w;
        *reinterpret_cast<float4*>(&Bs[brow][bcol]) =
            *reinterpret_cast<const float4*>(Qf + (size_t)(k0 + brow) * NDIM + n0 + bcol);
        __syncthreads();
        #pragma unroll
        for (int k = 0; k < 8; k++) {
            float4 a0 = *reinterpret_cast<const float4*>(&As[k][ty]);
            float4 a1 = *reinterpret_cast<const float4*>(&As[k][ty + 4]);
            float4 b0 = *reinterpret_cast<const float4*>(&Bs[k][tx]);
            float4 b1 = *reinterpret_cast<const float4*>(&Bs[k][tx + 4]);
            float a[8] = {a0.x, a0.y, a0.z, a0.w, a1.x, a1.y, a1.z, a1.w};
            float bb[8] = {b0.x, b0.y, b0.z, b0.w, b1.x, b1.y, b1.z, b1.w};
            #pragma unroll
            for (int i = 0; i < 8; i++)
                #pragma unroll
                for (int j = 0; j < 8; j++)
                    acc[i][j] = fmaf(a[i], bb[j], acc[i][j]);
        }
        __syncthreads();
    }

    const float* xb = x   + ((size_t)b * CDIM + o0) * NDIM;
    float*       ob = out + ((size_t)b * CDIM + o0) * NDIM;
    #pragma unroll
    for (int i = 0; i < 8; i++) {
        const int row = ty + i;
        const float bi = bo[o0 + row];
        float4 x0 = *reinterpret_cast<const float4*>(xb + (size_t)row * NDIM + n0 + tx);
        float4 x1 = *reinterpret_cast<const float4*>(xb + (size_t)row * NDIM + n0 + tx + 4);
        float* orow = ob + (size_t)row * NDIM + n0 + tx;
        *reinterpret_cast<float4*>(orow) = make_float4(
            acc[i][0] + bi + x0.x, acc[i][1] + bi + x0.y,
            acc[i][2] + bi + x0.z, acc[i][3] + bi + x0.w);
        *reinterpret_cast<float4*>(orow + 4) = make_float4(
            acc[i][4] + bi + x1.x, acc[i][5] + bi + x1.y,
            acc[i][6] + bi + x1.z, acc[i][7] + bi + x1.w);
    }
}

// ---------------------------------------------------------------------------
extern "C" void kernel_launch(void* const* d_in, const int* in_sizes, int n_in,
                              void* d_out, int out_size) {
    const float* x     = (const float*)d_in[0];
    const float* gamma = (const float*)d_in[1];
    const float* beta  = (const float*)d_in[2];
    const float* wq    = (const float*)d_in[3];
    const float* bq    = (const float*)d_in[4];
    const float* wk    = (const float*)d_in[5];
    const float* bk    = (const float*)d_in[6];
    const float* wv    = (const float*)d_in[7];
    const float* bv    = (const float*)d_in[8];
    const float* wo    = (const float*)d_in[9];
    const float* bo    = (const float*)d_in[10];
    float* out = (float*)d_out;

    k_stats<<<BATCH * GRP, 256>>>(x);
    k_qkv<<<dim3(NDIM / 128, 6, BATCH), 256>>>(x, wq, bq, wk, bk, wv, bv, gamma, beta);
    k_zero<<<(BATCH * CDIM * CDIM) / (256 * 4), 256>>>();
    k_kvmat<<<dim3(2, 2, BATCH * SPLITS), 256>>>();
    k_wokv<<<dim3(4, 4, BATCH), 256>>>(wo);
    k_out<<<dim3(NDIM / 128, 2, BATCH), 256>>>(x, bo, out);
}

// round 8
// speedup vs baseline: 1.5108x; 1.5108x over previous
#include <cuda_runtime.h>
#include <math.h>
#include <stdint.h>

// Problem dims (LinearAttnBlock: B=8, C=256, H=W=64)
#define BATCH 8
#define CDIM  256
#define NDIM  4096
#define GRP   32
#define KVSPLIT 8

// ---------------- scratch (__device__ globals; no allocation allowed) ------
__device__ float  g_qkv[(size_t)BATCH * 3 * CDIM * NDIM];            // [b][q/k/v][c][n]
__device__ float  g_kvp[(size_t)KVSPLIT * BATCH * CDIM * CDIM];      // per-split partials
__device__ float  g_M  [BATCH * CDIM * CDIM];                        // [b][o][c]
__device__ float2 g_stats[BATCH * GRP];                              // (mean, rstd)

// ---------------- tf32 mma.sync micro-kernel ------------------------------
static __device__ __forceinline__ uint32_t to_tf32(float f) {
    uint32_t r;
    asm("cvt.rna.tf32.f32 %0, %1;" : "=r"(r) : "f"(f));
    return r;
}

static __device__ __forceinline__ void mma_tf32(float c[4], const uint4& a, const uint2& b) {
    asm volatile(
        "mma.sync.aligned.m16n8k8.row.col.f32.tf32.tf32.f32 "
        "{%0,%1,%2,%3}, {%4,%5,%6,%7}, {%8,%9}, {%0,%1,%2,%3};"
        : "+f"(c[0]), "+f"(c[1]), "+f"(c[2]), "+f"(c[3])
        : "r"(a.x), "r"(a.y), "r"(a.z), "r"(a.w), "r"(b.x), "r"(b.y));
}

// Computes C[128,128] += A[128, NC*32] * B(k,n)[NC*32, 128] (tf32, fp32 acc).
// A: row-major, lda stride, k contiguous.
// BMODE 0: B source is S[k][n] (ldb stride per k-row), optional GroupNorm fold.
// BMODE 1: B source is S[col][k] (ldb stride per column, k contiguous).
// SMEM holds fragment-permuted tf32 tiles:
//   As[((mtile*4+ks)*32 + g*4 + t)*4 + hi + 2*kh]   (mtile=m/16, hi=(m/8)&1, g=m&7)
//   Bs[((ntile*4+ks)*32 + g*4 + t)*2 + kh]          (ntile=n/8, g=n&7)
// where k = ks*8 + kh*4 + t. Frag loads are then contiguous lds.128/lds.64.
template <int NC, int BMODE, bool GN>
static __device__ __forceinline__ void mma_block(
    const float* __restrict__ A, int lda,
    const float* __restrict__ B, int ldb,
    const float2* __restrict__ stats,
    const float* __restrict__ gamma, const float* __restrict__ beta,
    uint32_t* __restrict__ As, uint32_t* __restrict__ Bs,
    float C[2][8][4])
{
    const int tid = threadIdx.x;
    // A staging mapping: thread -> (row am, 16-float k half)
    const int am  = tid >> 1, akq = (tid & 1) << 4;
    const int amt = am >> 4, ahi = (am >> 3) & 1, ag = am & 7;
    // B staging mapping
    const int bk  = tid >> 3, bnq = (tid & 7) << 4;   // BMODE 0: row k, 16 n's
    const int bcl = tid >> 1, bkq = (tid & 1) << 4;   // BMODE 1: col, 16 k's
    // compute mapping
    const int lane = tid & 31, wid = tid >> 5;
    const int wm = wid & 3, wn = wid >> 2;

    float4 ra[4], rb[4];
    float sc = 1.f, sh = 0.f;

    // ---- prologue: load chunk 0 into regs ----
    {
        const float* pa = A + (size_t)am * lda + akq;
        #pragma unroll
        for (int q = 0; q < 4; q++) ra[q] = *(const float4*)(pa + q * 4);
        if (BMODE == 0) {
            if (GN) {
                const int c = bk;
                float2 ms = stats[c >> 3];
                sc = ms.y * gamma[c];
                sh = fmaf(-ms.x, sc, beta[c]);
            }
            const float* pb = B + (size_t)bk * ldb + bnq;
            #pragma unroll
            for (int q = 0; q < 4; q++) {
                float4 v = *(const float4*)(pb + q * 4);
                if (GN) {
                    v.x = fmaf(v.x, sc, sh); v.y = fmaf(v.y, sc, sh);
                    v.z = fmaf(v.z, sc, sh); v.w = fmaf(v.w, sc, sh);
                }
                rb[q] = v;
            }
        } else {
            const float* pb = B + (size_t)bcl * ldb + bkq;
            #pragma unroll
            for (int q = 0; q < 4; q++) rb[q] = *(const float4*)(pb + q * 4);
        }
    }

    #pragma unroll 1
    for (int i = 0; i < NC; i++) {
        // ---- store regs -> SMEM (cvt to tf32, permuted layout) ----
        #pragma unroll
        for (int q = 0; q < 4; q++) {
            const int k = akq + q * 4, ks = k >> 3, kh = (k >> 2) & 1;
            const int base = ((amt * 4 + ks) * 32 + ag * 4) * 4 + ahi + 2 * kh;
            As[base + 0]  = to_tf32(ra[q].x);
            As[base + 4]  = to_tf32(ra[q].y);
            As[base + 8]  = to_tf32(ra[q].z);
            As[base + 12] = to_tf32(ra[q].w);
        }
        if (BMODE == 0) {
            const int t = bk & 3, ks = bk >> 3, kh = (bk >> 2) & 1;
            #pragma unroll
            for (int q = 0; q < 4; q++) {
                const int n = bnq + q * 4;
                const float v[4] = {rb[q].x, rb[q].y, rb[q].z, rb[q].w};
                #pragma unroll
                for (int j = 0; j < 4; j++) {
                    const int nn = n + j, g = nn & 7, nt = nn >> 3;
                    Bs[((nt * 4 + ks) * 32 + g * 4 + t) * 2 + kh] = to_tf32(v[j]);
                }
            }
        } else {
            const int g = bcl & 7, nt = bcl >> 3;
            #pragma unroll
            for (int q = 0; q < 4; q++) {
                const int k = bkq + q * 4;
                const float v[4] = {rb[q].x, rb[q].y, rb[q].z, rb[q].w};
                #pragma unroll
                for (int j = 0; j < 4; j++) {
                    const int kk = k + j, ks = kk >> 3, kh = (kk >> 2) & 1, t = kk & 3;
                    Bs[((nt * 4 + ks) * 32 + g * 4 + t) * 2 + kh] = to_tf32(v[j]);
                }
            }
        }
        __syncthreads();

        // ---- prefetch chunk i+1 into regs (overlaps with mma below) ----
        if (i + 1 < NC) {
            const float* pa = A + (i + 1) * 32 + (size_t)am * lda + akq;
            #pragma unroll
            for (int q = 0; q < 4; q++) ra[q] = *(const float4*)(pa + q * 4);
            if (BMODE == 0) {
                if (GN) {
                    const int c = (i + 1) * 32 + bk;
                    float2 ms = stats[c >> 3];
                    sc = ms.y * gamma[c];
                    sh = fmaf(-ms.x, sc, beta[c]);
                }
                const float* pb = B + (size_t)((i + 1) * 32 + bk) * ldb + bnq;
                #pragma unroll
                for (int q = 0; q < 4; q++) {
                    float4 v = *(const float4*)(pb + q * 4);
                    if (GN) {
                        v.x = fmaf(v.x, sc, sh); v.y = fmaf(v.y, sc, sh);
                        v.z = fmaf(v.z, sc, sh); v.w = fmaf(v.w, sc, sh);
                    }
                    rb[q] = v;
                }
            } else {
                const float* pb = B + (size_t)bcl * ldb + (i + 1) * 32 + bkq;
                #pragma unroll
                for (int q = 0; q < 4; q++) rb[q] = *(const float4*)(pb + q * 4);
            }
        }

        // ---- compute: 4 k-steps x (2 m-tiles x 8 n-tiles) mma ----
        #pragma unroll
        for (int ks = 0; ks < 4; ks++) {
            uint4 af[2];
            #pragma unroll
            for (int mt = 0; mt < 2; mt++)
                af[mt] = *(const uint4*)&As[(((wm * 2 + mt) * 4 + ks) * 32 + lane) * 4];
            uint2 bf[8];
            #pragma unroll
            for (int nt = 0; nt < 8; nt++)
                bf[nt] = *(const uint2*)&Bs[(((wn * 8 + nt) * 4 + ks) * 32 + lane) * 2];
            #pragma unroll
            for (int mt = 0; mt < 2; mt++)
                #pragma unroll
                for (int nt = 0; nt < 8; nt++)
                    mma_tf32(C[mt][nt], af[mt], bf[nt]);
        }
        __syncthreads();
    }
}

// ---------------------------------------------------------------------------
// K1: GroupNorm statistics. One block per (b, g); group data contiguous.
// ---------------------------------------------------------------------------
__global__ __launch_bounds__(256) void k_stats(const float* __restrict__ x) {
    const int bg = blockIdx.x;
    const float4* p = reinterpret_cast<const float4*>(x + (size_t)bg * 8 * NDIM);
    float s = 0.f, s2 = 0.f;
    for (int i = threadIdx.x; i < 8 * NDIM / 4; i += 256) {
        float4 v = p[i];
        s  += v.x + v.y + v.z + v.w;
        s2 += v.x * v.x + v.y * v.y + v.z * v.z + v.w * v.w;
    }
    __shared__ float sh0[8], sh1[8];
    #pragma unroll
    for (int o = 16; o > 0; o >>= 1) {
        s  += __shfl_down_sync(0xffffffffu, s,  o);
        s2 += __shfl_down_sync(0xffffffffu, s2, o);
    }
    const int lane = threadIdx.x & 31, w = threadIdx.x >> 5;
    if (lane == 0) { sh0[w] = s; sh1[w] = s2; }
    __syncthreads();
    if (w == 0) {
        s  = (lane < 8) ? sh0[lane] : 0.f;
        s2 = (lane < 8) ? sh1[lane] : 0.f;
        #pragma unroll
        for (int o = 4; o > 0; o >>= 1) {
            s  += __shfl_down_sync(0xffffffffu, s,  o);
            s2 += __shfl_down_sync(0xffffffffu, s2, o);
        }
        if (lane == 0) {
            const float inv = 1.f / (8.f * NDIM);
            float mean = s * inv;
            float var  = s2 * inv - mean * mean;
            g_stats[bg] = make_float2(mean, rsqrtf(var + 1e-6f));
        }
    }
}

// ---------------------------------------------------------------------------
// K2: QKV = W_{q,k,v} @ GN(x) via tf32 mma.sync. GN folded into B staging,
// bias + elu+1 in epilogue. Output [b][q/k/v][c][n].
// ---------------------------------------------------------------------------
__global__ __launch_bounds__(256) void k_qkv_t(
    const float* __restrict__ x,
    const float* __restrict__ wq, const float* __restrict__ bq,
    const float* __restrict__ wk, const float* __restrict__ bk,
    const float* __restrict__ wv, const float* __restrict__ bv,
    const float* __restrict__ gamma, const float* __restrict__ beta)
{
    __shared__ uint32_t As[4096], Bs[4096];
    const int b  = blockIdx.z;
    const int by = blockIdx.y;            // 0..5
    const int which = by >> 1;            // 0=q 1=k 2=v
    const int m0 = (by & 1) * 128;
    const int n0 = blockIdx.x * 128;
    const float* W    = which == 0 ? wq : which == 1 ? wk : wv;
    const float* bias = which == 0 ? bq : which == 1 ? bk : bv;

    float C[2][8][4];
    #pragma unroll
    for (int mt = 0; mt < 2; mt++)
        #pragma unroll
        for (int nt = 0; nt < 8; nt++)
            #pragma unroll
            for (int r = 0; r < 4; r++) C[mt][nt][r] = 0.f;

    mma_block<8, 0, true>(W + (size_t)m0 * CDIM, CDIM,
                          x + (size_t)b * CDIM * NDIM + n0, NDIM,
                          g_stats + b * GRP, gamma, beta, As, Bs, C);

    const int lane = threadIdx.x & 31, wid = threadIdx.x >> 5;
    const int g = lane >> 2, t = lane & 3, wm = wid & 3, wn = wid >> 2;
    const bool act = (which < 2);
    float* outp = g_qkv + (((size_t)b * 3 + which) * CDIM + m0) * NDIM + n0;
    #pragma unroll
    for (int mt = 0; mt < 2; mt++) {
        const int r0 = wm * 32 + mt * 16 + g;
        const float b0v = bias[m0 + r0], b1v = bias[m0 + r0 + 8];
        #pragma unroll
        for (int nt = 0; nt < 8; nt++) {
            const int col = wn * 64 + nt * 8 + 2 * t;
            float v0 = C[mt][nt][0] + b0v, v1 = C[mt][nt][1] + b0v;
            float v2 = C[mt][nt][2] + b1v, v3 = C[mt][nt][3] + b1v;
            if (act) {
                v0 = (v0 > 0.f) ? (v0 + 1.f) : expf(v0);
                v1 = (v1 > 0.f) ? (v1 + 1.f) : expf(v1);
                v2 = (v2 > 0.f) ? (v2 + 1.f) : expf(v2);
                v3 = (v3 > 0.f) ? (v3 + 1.f) : expf(v3);
            }
            *(float2*)(outp + (size_t)r0 * NDIM + col)       = make_float2(v0, v1);
            *(float2*)(outp + (size_t)(r0 + 8) * NDIM + col) = make_float2(v2, v3);
        }
    }
}

// ---------------------------------------------------------------------------
// K3: kv partials. kvp[sp][b][c][d] = sum_{n in split sp} K[c,n] V[d,n].
// tf32 mma.sync; each split writes its own buffer (no atomics).
// ---------------------------------------------------------------------------
__global__ __launch_bounds__(256) void k_kv_t() {
    __shared__ uint32_t As[4096], Bs[4096];
    const int z = blockIdx.z;
    const int b = z / KVSPLIT, sp = z % KVSPLIT;
    const int c0 = blockIdx.y * 128, d0 = blockIdx.x * 128;
    const int nb = sp * (NDIM / KVSPLIT);
    const float* Kf = g_qkv + ((size_t)b * 3 + 1) * CDIM * NDIM;
    const float* Vf = g_qkv + ((size_t)b * 3 + 2) * CDIM * NDIM;

    float C[2][8][4];
    #pragma unroll
    for (int mt = 0; mt < 2; mt++)
        #pragma unroll
        for (int nt = 0; nt < 8; nt++)
            #pragma unroll
            for (int r = 0; r < 4; r++) C[mt][nt][r] = 0.f;

    mma_block<(NDIM / KVSPLIT) / 32, 1, false>(
        Kf + (size_t)c0 * NDIM + nb, NDIM,
        Vf + (size_t)d0 * NDIM + nb, NDIM,
        nullptr, nullptr, nullptr, As, Bs, C);

    const int lane = threadIdx.x & 31, wid = threadIdx.x >> 5;
    const int g = lane >> 2, t = lane & 3, wm = wid & 3, wn = wid >> 2;
    float* dst = g_kvp + ((size_t)sp * BATCH + b) * CDIM * CDIM;
    #pragma unroll
    for (int mt = 0; mt < 2; mt++) {
        const int r0 = c0 + wm * 32 + mt * 16 + g;
        #pragma unroll
        for (int nt = 0; nt < 8; nt++) {
            const int col = d0 + wn * 64 + nt * 8 + 2 * t;
            *(float2*)(dst + (size_t)r0 * CDIM + col)       = make_float2(C[mt][nt][0], C[mt][nt][1]);
            *(float2*)(dst + (size_t)(r0 + 8) * CDIM + col) = make_float2(C[mt][nt][2], C[mt][nt][3]);
        }
    }
}

// ---------------------------------------------------------------------------
// K4: M[b][o][c] = sum_d wo[o,d] * kv[b][c][d], summing the 8 split
// partials during B staging. Tiny fp32 GEMM.
// ---------------------------------------------------------------------------
__global__ __launch_bounds__(256) void k_wokv(const float* __restrict__ wo) {
    const int b  = blockIdx.z;
    const int o0 = blockIdx.y * 64, c0 = blockIdx.x * 64;
    const float* kvb = g_kvp + (size_t)b * CDIM * CDIM;
    const size_t SS = (size_t)BATCH * CDIM * CDIM;

    __shared__ float As[16][64];
    __shared__ float Bs[16][64];
    const int tid  = threadIdx.x;
    const int arow = tid >> 2, acol = (tid & 3) << 2;
    const int tx = (tid & 15) << 2, ty = (tid >> 4) << 2;

    float acc[4][4];
    #pragma unroll
    for (int i = 0; i < 4; i++)
        #pragma unroll
        for (int j = 0; j < 4; j++) acc[i][j] = 0.f;

    for (int k0 = 0; k0 < CDIM; k0 += 16) {
        float4 av = *reinterpret_cast<const float4*>(wo + (o0 + arow) * CDIM + k0 + acol);
        As[acol + 0][arow] = av.x; As[acol + 1][arow] = av.y;
        As[acol + 2][arow] = av.z; As[acol + 3][arow] = av.w;
        const float* bp = kvb + (size_t)(c0 + arow) * CDIM + k0 + acol;
        float4 bv = *reinterpret_cast<const float4*>(bp);
        #pragma unroll
        for (int s = 1; s < KVSPLIT; s++) {
            float4 pv = *reinterpret_cast<const float4*>(bp + s * SS);
            bv.x += pv.x; bv.y += pv.y; bv.z += pv.z; bv.w += pv.w;
        }
        Bs[acol + 0][arow] = bv.x; Bs[acol + 1][arow] = bv.y;
        Bs[acol + 2][arow] = bv.z; Bs[acol + 3][arow] = bv.w;
        __syncthreads();
        #pragma unroll
        for (int k = 0; k < 16; k++) {
            float4 a4 = *reinterpret_cast<const float4*>(&As[k][ty]);
            float4 b4 = *reinterpret_cast<const float4*>(&Bs[k][tx]);
            float a[4] = {a4.x, a4.y, a4.z, a4.w};
            float bb[4] = {b4.x, b4.y, b4.z, b4.w};
            #pragma unroll
            for (int i = 0; i < 4; i++)
                #pragma unroll
                for (int j = 0; j < 4; j++)
                    acc[i][j] = fmaf(a[i], bb[j], acc[i][j]);
        }
        __syncthreads();
    }
    float* Mb = g_M + (size_t)b * CDIM * CDIM;
    #pragma unroll
    for (int i = 0; i < 4; i++)
        *reinterpret_cast<float4*>(Mb + (size_t)(o0 + ty + i) * CDIM + c0 + tx) =
            make_float4(acc[i][0], acc[i][1], acc[i][2], acc[i][3]);
}

// ---------------------------------------------------------------------------
// K5: out[b][o][n] = x[b][o][n] + M[b][o,:] . Q[:,n] + bo[o].
// tf32 mma.sync + fused residual epilogue.
// ---------------------------------------------------------------------------
__global__ __launch_bounds__(256) void k_out_t(const float* __restrict__ x,
                                               const float* __restrict__ bo,
                                               float* __restrict__ out) {
    __shared__ uint32_t As[4096], Bs[4096];
    const int b  = blockIdx.z;
    const int o0 = blockIdx.y * 128, n0 = blockIdx.x * 128;
    const float* Mb = g_M + (size_t)b * CDIM * CDIM;
    const float* Qf = g_qkv + (size_t)b * 3 * CDIM * NDIM;   // q plane, [c][n]

    float C[2][8][4];
    #pragma unroll
    for (int mt = 0; mt < 2; mt++)
        #pragma unroll
        for (int nt = 0; nt < 8; nt++)
            #pragma unroll
            for (int r = 0; r < 4; r++) C[mt][nt][r] = 0.f;

    mma_block<8, 0, false>(Mb + (size_t)o0 * CDIM, CDIM,
                           Qf + n0, NDIM,
                           nullptr, nullptr, nullptr, As, Bs, C);

    const int lane = threadIdx.x & 31, wid = threadIdx.x >> 5;
    const int g = lane >> 2, t = lane & 3, wm = wid & 3, wn = wid >> 2;
    const float* xb = x   + ((size_t)b * CDIM + o0) * NDIM + n0;
    float*       ob = out + ((size_t)b * CDIM + o0) * NDIM + n0;
    #pragma unroll
    for (int mt = 0; mt < 2; mt++) {
        const int r0 = wm * 32 + mt * 16 + g;
        const float b0v = bo[o0 + r0], b1v = bo[o0 + r0 + 8];
        #pragma unroll
        for (int nt = 0; nt < 8; nt++) {
            const int col = wn * 64 + nt * 8 + 2 * t;
            float2 x0 = *(const float2*)(xb + (size_t)r0 * NDIM + col);
            float2 x1 = *(const float2*)(xb + (size_t)(r0 + 8) * NDIM + col);
            *(float2*)(ob + (size_t)r0 * NDIM + col) =
                make_float2(C[mt][nt][0] + b0v + x0.x, C[mt][nt][1] + b0v + x0.y);
            *(float2*)(ob + (size_t)(r0 + 8) * NDIM + col) =
                make_float2(C[mt][nt][2] + b1v + x1.x, C[mt][nt][3] + b1v + x1.y);
        }
    }
}

// ---------------------------------------------------------------------------
extern "C" void kernel_launch(void* const* d_in, const int* in_sizes, int n_in,
                              void* d_out, int out_size) {
    const float* x     = (const float*)d_in[0];
    const float* gamma = (const float*)d_in[1];
    const float* beta  = (const float*)d_in[2];
    const float* wq    = (const float*)d_in[3];
    const float* bq    = (const float*)d_in[4];
    const float* wk    = (const float*)d_in[5];
    const float* bk    = (const float*)d_in[6];
    const float* wv    = (const float*)d_in[7];
    const float* bv    = (const float*)d_in[8];
    const float* wo    = (const float*)d_in[9];
    const float* bo    = (const float*)d_in[10];
    float* out = (float*)d_out;

    k_stats<<<BATCH * GRP, 256>>>(x);
    k_qkv_t<<<dim3(NDIM / 128, 6, BATCH), 256>>>(x, wq, bq, wk, bk, wv, bv, gamma, beta);
    k_kv_t<<<dim3(2, 2, BATCH * KVSPLIT), 256>>>();
    k_wokv<<<dim3(4, 4, BATCH), 256>>>(wo);
    k_out_t<<<dim3(NDIM / 128, 2, BATCH), 256>>>(x, bo, out);
}

// round 9
// speedup vs baseline: 1.7233x; 1.1407x over previous
#include <cuda_runtime.h>
#include <math.h>
#include <stdint.h>

// Problem dims (LinearAttnBlock: B=8, C=256, H=W=64)
#define BATCH 8
#define CDIM  256
#define NDIM  4096
#define GRP   32
#define KVSPLIT 8

// ---------------- scratch (__device__ globals; no allocation allowed) ------
__device__ float  g_qkv[(size_t)BATCH * 2 * CDIM * NDIM];        // [b][q/k][c][n]
__device__ float  g_Sp [(size_t)KVSPLIT * BATCH * CDIM * CDIM];  // S split partials
__device__ float  g_S  [BATCH * CDIM * CDIM];                    // [b][c][e] = K.h^T
__device__ float  g_M  [BATCH * CDIM * CDIM];                    // [b][o][c]
__device__ float  g_U  [CDIM * CDIM];                            // wo @ Wv
__device__ float  g_wt [CDIM];                                   // wo @ bv
__device__ float  g_k1 [BATCH * CDIM];                           // rowsum of K
__device__ float2 g_stats[BATCH * GRP];                          // (mean, rstd)

// ---------------- tf32 mma.sync micro-kernel ------------------------------
static __device__ __forceinline__ uint32_t to_tf32(float f) {
    uint32_t r;
    asm("cvt.rna.tf32.f32 %0, %1;" : "=r"(r) : "f"(f));
    return r;
}

static __device__ __forceinline__ void mma_tf32(float c[4], const uint4& a, const uint2& b) {
    asm volatile(
        "mma.sync.aligned.m16n8k8.row.col.f32.tf32.tf32.f32 "
        "{%0,%1,%2,%3}, {%4,%5,%6,%7}, {%8,%9}, {%0,%1,%2,%3};"
        : "+f"(c[0]), "+f"(c[1]), "+f"(c[2]), "+f"(c[3])
        : "r"(a.x), "r"(a.y), "r"(a.z), "r"(a.w), "r"(b.x), "r"(b.y));
}

// C[128,128] += A[128, NC*32] * B(k,n)[NC*32, 128] (tf32, fp32 acc).
// A: row-major, lda stride, k contiguous.
// BMODE 0: B source is S[k][n] (ldb per k-row); GN = per-k affine from stats.
// BMODE 1: B source is S[col][k] (ldb per col, k contig); GN = per-thread
//          constant affine (scB, shB) -- caller computes for its staging row.
// SMEM fragment-permuted tf32 tiles, double-buffered (2 x 16KB per operand):
//   As[((mtile*4+ks)*32 + g*4 + t)*4 + hi + 2*kh]
//   Bs[((ntile*4+ks)*32 + g*4 + t)*2 + kh]
template <int NC, int BMODE, bool GN>
static __device__ __forceinline__ void mma_block(
    const float* __restrict__ A, int lda,
    const float* __restrict__ B, int ldb,
    const float2* __restrict__ stats,
    const float* __restrict__ gamma, const float* __restrict__ beta,
    float scB, float shB,
    uint32_t* __restrict__ As, uint32_t* __restrict__ Bs,
    float C[2][8][4])
{
    const int tid = threadIdx.x;
    const int am  = tid >> 1, akq = (tid & 1) << 4;
    const int amt = am >> 4, ahi = (am >> 3) & 1, ag = am & 7;
    const int bk  = tid >> 3, bnq = (tid & 7) << 4;   // BMODE 0
    const int bcl = tid >> 1, bkq = (tid & 1) << 4;   // BMODE 1
    const int lane = tid & 31, wid = tid >> 5;
    const int wm = wid & 3, wn = wid >> 2;

    float4 ra[4], rb[4];
    float sc = scB, sh = shB;

    // ---- prologue: load chunk 0 into regs ----
    {
        const float* pa = A + (size_t)am * lda + akq;
        #pragma unroll
        for (int q = 0; q < 4; q++) ra[q] = *(const float4*)(pa + q * 4);
        if (BMODE == 0) {
            if (GN) {
                float2 ms = stats[bk >> 3];
                sc = ms.y * gamma[bk];
                sh = fmaf(-ms.x, sc, beta[bk]);
            }
            const float* pb = B + (size_t)bk * ldb + bnq;
            #pragma unroll
            for (int q = 0; q < 4; q++) {
                float4 v = *(const float4*)(pb + q * 4);
                if (GN) {
                    v.x = fmaf(v.x, sc, sh); v.y = fmaf(v.y, sc, sh);
                    v.z = fmaf(v.z, sc, sh); v.w = fmaf(v.w, sc, sh);
                }
                rb[q] = v;
            }
        } else {
            const float* pb = B + (size_t)bcl * ldb + bkq;
            #pragma unroll
            for (int q = 0; q < 4; q++) {
                float4 v = *(const float4*)(pb + q * 4);
                if (GN) {
                    v.x = fmaf(v.x, sc, sh); v.y = fmaf(v.y, sc, sh);
                    v.z = fmaf(v.z, sc, sh); v.w = fmaf(v.w, sc, sh);
                }
                rb[q] = v;
            }
        }
    }

    #pragma unroll 1
    for (int i = 0; i < NC; i++) {
        uint32_t* Asb = As + (i & 1) * 4096;
        uint32_t* Bsb = Bs + (i & 1) * 4096;
        // ---- store regs -> SMEM stage (cvt to tf32, permuted layout) ----
        #pragma unroll
        for (int q = 0; q < 4; q++) {
            const int k = akq + q * 4, ks = k >> 3, kh = (k >> 2) & 1;
            const int base = ((amt * 4 + ks) * 32 + ag * 4) * 4 + ahi + 2 * kh;
            Asb[base + 0]  = to_tf32(ra[q].x);
            Asb[base + 4]  = to_tf32(ra[q].y);
            Asb[base + 8]  = to_tf32(ra[q].z);
            Asb[base + 12] = to_tf32(ra[q].w);
        }
        if (BMODE == 0) {
            const int t = bk & 3, ks = bk >> 3, kh = (bk >> 2) & 1;
            #pragma unroll
            for (int q = 0; q < 4; q++) {
                const int n = bnq + q * 4;
                const float v[4] = {rb[q].x, rb[q].y, rb[q].z, rb[q].w};
                #pragma unroll
                for (int j = 0; j < 4; j++) {
                    const int nn = n + j, g = nn & 7, nt = nn >> 3;
                    Bsb[((nt * 4 + ks) * 32 + g * 4 + t) * 2 + kh] = to_tf32(v[j]);
                }
            }
        } else {
            const int g = bcl & 7, nt = bcl >> 3;
            #pragma unroll
            for (int q = 0; q < 4; q++) {
                const int k = bkq + q * 4;
                const float v[4] = {rb[q].x, rb[q].y, rb[q].z, rb[q].w};
                #pragma unroll
                for (int j = 0; j < 4; j++) {
                    const int kk = k + j, ks = kk >> 3, kh = (kk >> 2) & 1, t = kk & 3;
                    Bsb[((nt * 4 + ks) * 32 + g * 4 + t) * 2 + kh] = to_tf32(v[j]);
                }
            }
        }
        __syncthreads();   // single sync per chunk (double-buffered stages)

        // ---- prefetch chunk i+1 into regs (overlaps with mma below) ----
        if (i + 1 < NC) {
            const float* pa = A + (i + 1) * 32 + (size_t)am * lda + akq;
            #pragma unroll
            for (int q = 0; q < 4; q++) ra[q] = *(const float4*)(pa + q * 4);
            if (BMODE == 0) {
                if (GN) {
                    const int c = (i + 1) * 32 + bk;
                    float2 ms = stats[c >> 3];
                    sc = ms.y * gamma[c];
                    sh = fmaf(-ms.x, sc, beta[c]);
                }
                const float* pb = B + (size_t)((i + 1) * 32 + bk) * ldb + bnq;
                #pragma unroll
                for (int q = 0; q < 4; q++) {
                    float4 v = *(const float4*)(pb + q * 4);
                    if (GN) {
                        v.x = fmaf(v.x, sc, sh); v.y = fmaf(v.y, sc, sh);
                        v.z = fmaf(v.z, sc, sh); v.w = fmaf(v.w, sc, sh);
                    }
                    rb[q] = v;
                }
            } else {
                const float* pb = B + (size_t)bcl * ldb + (i + 1) * 32 + bkq;
                #pragma unroll
                for (int q = 0; q < 4; q++) {
                    float4 v = *(const float4*)(pb + q * 4);
                    if (GN) {
                        v.x = fmaf(v.x, sc, sh); v.y = fmaf(v.y, sc, sh);
                        v.z = fmaf(v.z, sc, sh); v.w = fmaf(v.w, sc, sh);
                    }
                    rb[q] = v;
                }
            }
        }

        // ---- compute: 4 k-steps x (2 m-tiles x 8 n-tiles) mma ----
        #pragma unroll
        for (int ks = 0; ks < 4; ks++) {
            uint4 af[2];
            #pragma unroll
            for (int mt = 0; mt < 2; mt++)
                af[mt] = *(const uint4*)&Asb[(((wm * 2 + mt) * 4 + ks) * 32 + lane) * 4];
            uint2 bf[8];
            #pragma unroll
            for (int nt = 0; nt < 8; nt++)
                bf[nt] = *(const uint2*)&Bsb[(((wn * 8 + nt) * 4 + ks) * 32 + lane) * 2];
            #pragma unroll
            for (int mt = 0; mt < 2; mt++)
                #pragma unroll
                for (int nt = 0; nt < 8; nt++)
                    mma_tf32(C[mt][nt], af[mt], bf[nt]);
        }
    }
    __syncthreads();   // protect SMEM reuse by epilogues
}

// ---------------------------------------------------------------------------
// K1: GroupNorm statistics (one block per (b,g)) + zero g_k1 for this replay.
// ---------------------------------------------------------------------------
__global__ __launch_bounds__(256) void k_stats(const float* __restrict__ x) {
    const int bg = blockIdx.x;
    if (threadIdx.x < 8) g_k1[bg * 8 + threadIdx.x] = 0.f;
    const float4* p = reinterpret_cast<const float4*>(x + (size_t)bg * 8 * NDIM);
    float s = 0.f, s2 = 0.f;
    for (int i = threadIdx.x; i < 8 * NDIM / 4; i += 256) {
        float4 v = p[i];
        s  += v.x + v.y + v.z + v.w;
        s2 += v.x * v.x + v.y * v.y + v.z * v.z + v.w * v.w;
    }
    __shared__ float sh0[8], sh1[8];
    #pragma unroll
    for (int o = 16; o > 0; o >>= 1) {
        s  += __shfl_down_sync(0xffffffffu, s,  o);
        s2 += __shfl_down_sync(0xffffffffu, s2, o);
    }
    const int lane = threadIdx.x & 31, w = threadIdx.x >> 5;
    if (lane == 0) { sh0[w] = s; sh1[w] = s2; }
    __syncthreads();
    if (w == 0) {
        s  = (lane < 8) ? sh0[lane] : 0.f;
        s2 = (lane < 8) ? sh1[lane] : 0.f;
        #pragma unroll
        for (int o = 4; o > 0; o >>= 1) {
            s  += __shfl_down_sync(0xffffffffu, s,  o);
            s2 += __shfl_down_sync(0xffffffffu, s2, o);
        }
        if (lane == 0) {
            const float inv = 1.f / (8.f * NDIM);
            float mean = s * inv;
            float var  = s2 * inv - mean * mean;
            g_stats[bg] = make_float2(mean, rsqrtf(var + 1e-6f));
        }
    }
}

// ---------------------------------------------------------------------------
// K2: Q,K = W_{q,k} @ GN(x) via tf32 mma.sync (GN folded into B staging).
// bias + elu+1 epilogue; K path also accumulates k1 rowsums (atomicAdd).
// ---------------------------------------------------------------------------
__global__ __launch_bounds__(256) void k_qkv_t(
    const float* __restrict__ x,
    const float* __restrict__ wq, const float* __restrict__ bq,
    const float* __restrict__ wk, const float* __restrict__ bk,
    const float* __restrict__ gamma, const float* __restrict__ beta)
{
    extern __shared__ uint32_t smp[];
    uint32_t* As = smp;            // 2 x 4096
    uint32_t* Bs = smp + 8192;     // 2 x 4096
    const int b  = blockIdx.z;
    const int by = blockIdx.y;            // 0..3
    const int which = by >> 1;            // 0=q 1=k
    const int m0 = (by & 1) * 128;
    const int n0 = blockIdx.x * 128;
    const float* W    = which == 0 ? wq : wk;
    const float* bias = which == 0 ? bq : bk;

    float C[2][8][4];
    #pragma unroll
    for (int mt = 0; mt < 2; mt++)
        #pragma unroll
        for (int nt = 0; nt < 8; nt++)
            #pragma unroll
            for (int r = 0; r < 4; r++) C[mt][nt][r] = 0.f;

    mma_block<8, 0, true>(W + (size_t)m0 * CDIM, CDIM,
                          x + (size_t)b * CDIM * NDIM + n0, NDIM,
                          g_stats + b * GRP, gamma, beta, 1.f, 0.f, As, Bs, C);

    const int lane = threadIdx.x & 31, wid = threadIdx.x >> 5;
    const int g = lane >> 2, t = lane & 3, wm = wid & 3, wn = wid >> 2;
    float* outp = g_qkv + (((size_t)b * 2 + which) * CDIM + m0) * NDIM + n0;
    float rs0[2] = {0.f, 0.f}, rs1[2] = {0.f, 0.f};
    #pragma unroll
    for (int mt = 0; mt < 2; mt++) {
        const int r0 = wm * 32 + mt * 16 + g;
        const float b0v = bias[m0 + r0], b1v = bias[m0 + r0 + 8];
        #pragma unroll
        for (int nt = 0; nt < 8; nt++) {
            const int col = wn * 64 + nt * 8 + 2 * t;
            float v0 = C[mt][nt][0] + b0v, v1 = C[mt][nt][1] + b0v;
            float v2 = C[mt][nt][2] + b1v, v3 = C[mt][nt][3] + b1v;
            v0 = (v0 > 0.f) ? (v0 + 1.f) : expf(v0);   // elu+1
            v1 = (v1 > 0.f) ? (v1 + 1.f) : expf(v1);
            v2 = (v2 > 0.f) ? (v2 + 1.f) : expf(v2);
            v3 = (v3 > 0.f) ? (v3 + 1.f) : expf(v3);
            rs0[mt] += v0 + v1;
            rs1[mt] += v2 + v3;
            *(float2*)(outp + (size_t)r0 * NDIM + col)       = make_float2(v0, v1);
            *(float2*)(outp + (size_t)(r0 + 8) * NDIM + col) = make_float2(v2, v3);
        }
    }
    if (which == 1) {   // k1[c] = sum_n K[c,n]
        #pragma unroll
        for (int mt = 0; mt < 2; mt++) {
            float a = rs0[mt], c2 = rs1[mt];
            a  += __shfl_xor_sync(0xffffffffu, a,  1);
            a  += __shfl_xor_sync(0xffffffffu, a,  2);
            c2 += __shfl_xor_sync(0xffffffffu, c2, 1);
            c2 += __shfl_xor_sync(0xffffffffu, c2, 2);
            if (t == 0) {
                const int r0 = wm * 32 + mt * 16 + g;
                atomicAdd(&g_k1[b * CDIM + m0 + r0], a);
                atomicAdd(&g_k1[b * CDIM + m0 + r0 + 8], c2);
            }
        }
    }
}

// ---------------------------------------------------------------------------
// K3: S partials. Sp[sp][b][c][e] = sum_{n in split} K[c,n] * GN(x)[e,n].
// GN fold is a per-thread constant (row e fixed per staging thread).
// ---------------------------------------------------------------------------
__global__ __launch_bounds__(256) void k_S(const float* __restrict__ x,
                                           const float* __restrict__ gamma,
                                           const float* __restrict__ beta) {
    extern __shared__ uint32_t smp[];
    uint32_t* As = smp;
    uint32_t* Bs = smp + 8192;
    const int z = blockIdx.z;
    const int b = z / KVSPLIT, sp = z % KVSPLIT;
    const int c0 = blockIdx.y * 128, e0 = blockIdx.x * 128;
    const int nb = sp * (NDIM / KVSPLIT);
    const float* Kf = g_qkv + ((size_t)b * 2 + 1) * CDIM * NDIM;

    const int e = e0 + (threadIdx.x >> 1);     // staging row for BMODE 1
    float2 ms = g_stats[b * GRP + (e >> 3)];
    const float sc = ms.y * gamma[e];
    const float sh = fmaf(-ms.x, sc, beta[e]);

    float C[2][8][4];
    #pragma unroll
    for (int mt = 0; mt < 2; mt++)
        #pragma unroll
        for (int nt = 0; nt < 8; nt++)
            #pragma unroll
            for (int r = 0; r < 4; r++) C[mt][nt][r] = 0.f;

    mma_block<(NDIM / KVSPLIT) / 32, 1, true>(
        Kf + (size_t)c0 * NDIM + nb, NDIM,
        x + ((size_t)b * CDIM + e0) * NDIM + nb, NDIM,
        nullptr, nullptr, nullptr, sc, sh, As, Bs, C);

    const int lane = threadIdx.x & 31, wid = threadIdx.x >> 5;
    const int g = lane >> 2, t = lane & 3, wm = wid & 3, wn = wid >> 2;
    float* dst = g_Sp + ((size_t)sp * BATCH + b) * CDIM * CDIM;
    #pragma unroll
    for (int mt = 0; mt < 2; mt++) {
        const int r0 = c0 + wm * 32 + mt * 16 + g;
        #pragma unroll
        for (int nt = 0; nt < 8; nt++) {
            const int col = e0 + wn * 64 + nt * 8 + 2 * t;
            *(float2*)(dst + (size_t)r0 * CDIM + col)       = make_float2(C[mt][nt][0], C[mt][nt][1]);
            *(float2*)(dst + (size_t)(r0 + 8) * CDIM + col) = make_float2(C[mt][nt][2], C[mt][nt][3]);
        }
    }
}

// ---------------------------------------------------------------------------
// K4: streaming reduction of the 8 S partials.
// ---------------------------------------------------------------------------
__global__ __launch_bounds__(256) void k_red() {
    const size_t i = (size_t)blockIdx.x * 256 + threadIdx.x;   // float4 idx
    const size_t SS = (size_t)BATCH * CDIM * CDIM / 4;
    const float4* p = reinterpret_cast<const float4*>(g_Sp);
    float4 a = p[i];
    #pragma unroll
    for (int s = 1; s < KVSPLIT; s++) {
        float4 v = p[i + (size_t)s * SS];
        a.x += v.x; a.y += v.y; a.z += v.z; a.w += v.w;
    }
    reinterpret_cast<float4*>(g_S)[i] = a;
}

// ---------------------------------------------------------------------------
// K5: U = wo @ Wv (batch-independent) and wt = wo @ bv. fp32, tiny.
// ---------------------------------------------------------------------------
__global__ __launch_bounds__(256) void k_prep(const float* __restrict__ wo,
                                              const float* __restrict__ wv,
                                              const float* __restrict__ bv) {
    const int o0 = blockIdx.y * 64, e0 = blockIdx.x * 64;
    const int tid = threadIdx.x;
    if (blockIdx.x == 0 && tid < 64) {        // wt for this o-range
        const float* wr = wo + (size_t)(o0 + tid) * CDIM;
        float s = 0.f;
        for (int d = 0; d < CDIM; d += 4) {
            float4 w4 = *(const float4*)(wr + d);
            float4 b4 = *(const float4*)(bv + d);
            s += w4.x * b4.x + w4.y * b4.y + w4.z * b4.z + w4.w * b4.w;
        }
        g_wt[o0 + tid] = s;
    }

    __shared__ float As[16][64];
    __shared__ float Bs[16][64];
    const int arow = tid >> 2, acol = (tid & 3) << 2;   // A^T staging
    const int brow = tid >> 4, bcol = (tid & 15) << 2;  // B row-major staging
    const int tx = (tid & 15) << 2, ty = (tid >> 4) << 2;

    float acc[4][4];
    #pragma unroll
    for (int i = 0; i < 4; i++)
        #pragma unroll
        for (int j = 0; j < 4; j++) acc[i][j] = 0.f;

    for (int k0 = 0; k0 < CDIM; k0 += 16) {
        float4 av = *(const float4*)(wo + (size_t)(o0 + arow) * CDIM + k0 + acol);
        As[acol + 0][arow] = av.x; As[acol + 1][arow] = av.y;
        As[acol + 2][arow] = av.z; As[acol + 3][arow] = av.w;
        *(float4*)&Bs[brow][bcol] =
            *(const float4*)(wv + (size_t)(k0 + brow) * CDIM + e0 + bcol);
        __syncthreads();
        #pragma unroll
        for (int k = 0; k < 16; k++) {
            float4 a4 = *(const float4*)&As[k][ty];
            float4 b4 = *(const float4*)&Bs[k][tx];
            float a[4] = {a4.x, a4.y, a4.z, a4.w};
            float bb[4] = {b4.x, b4.y, b4.z, b4.w};
            #pragma unroll
            for (int i = 0; i < 4; i++)
                #pragma unroll
                for (int j = 0; j < 4; j++)
                    acc[i][j] = fmaf(a[i], bb[j], acc[i][j]);
        }
        __syncthreads();
    }
    #pragma unroll
    for (int i = 0; i < 4; i++)
        *(float4*)(g_U + (size_t)(o0 + ty + i) * CDIM + e0 + tx) =
            make_float4(acc[i][0], acc[i][1], acc[i][2], acc[i][3]);
}

// ---------------------------------------------------------------------------
// K6: M[b][o][c] = sum_e U[o,e] S[b][c,e] + wt[o] * k1[b][c]. fp32, tiny.
// ---------------------------------------------------------------------------
__global__ __launch_bounds__(256) void k_M() {
    const int b  = blockIdx.z;
    const int o0 = blockIdx.y * 64, c0 = blockIdx.x * 64;
    const float* Sb = g_S + (size_t)b * CDIM * CDIM;

    __shared__ float As[16][64];
    __shared__ float Bs[16][64];
    const int tid  = threadIdx.x;
    const int arow = tid >> 2, acol = (tid & 3) << 2;
    const int tx = (tid & 15) << 2, ty = (tid >> 4) << 2;

    float acc[4][4];
    #pragma unroll
    for (int i = 0; i < 4; i++)
        #pragma unroll
        for (int j = 0; j < 4; j++) acc[i][j] = 0.f;

    for (int k0 = 0; k0 < CDIM; k0 += 16) {
        float4 av = *(const float4*)(g_U + (size_t)(o0 + arow) * CDIM + k0 + acol);
        As[acol + 0][arow] = av.x; As[acol + 1][arow] = av.y;
        As[acol + 2][arow] = av.z; As[acol + 3][arow] = av.w;
        float4 bv = *(const float4*)(Sb + (size_t)(c0 + arow) * CDIM + k0 + acol);
        Bs[acol + 0][arow] = bv.x; Bs[acol + 1][arow] = bv.y;
        Bs[acol + 2][arow] = bv.z; Bs[acol + 3][arow] = bv.w;
        __syncthreads();
        #pragma unroll
        for (int k = 0; k < 16; k++) {
            float4 a4 = *(const float4*)&As[k][ty];
            float4 b4 = *(const float4*)&Bs[k][tx];
            float a[4] = {a4.x, a4.y, a4.z, a4.w};
            float bb[4] = {b4.x, b4.y, b4.z, b4.w};
            #pragma unroll
            for (int i = 0; i < 4; i++)
                #pragma unroll
                for (int j = 0; j < 4; j++)
                    acc[i][j] = fmaf(a[i], bb[j], acc[i][j]);
        }
        __syncthreads();
    }
    float* Mb = g_M + (size_t)b * CDIM * CDIM;
    const float* k1b = g_k1 + b * CDIM;
    #pragma unroll
    for (int i = 0; i < 4; i++) {
        const float w = g_wt[o0 + ty + i];
        *(float4*)(Mb + (size_t)(o0 + ty + i) * CDIM + c0 + tx) = make_float4(
            acc[i][0] + w * k1b[c0 + tx + 0], acc[i][1] + w * k1b[c0 + tx + 1],
            acc[i][2] + w * k1b[c0 + tx + 2], acc[i][3] + w * k1b[c0 + tx + 3]);
    }
}

// ---------------------------------------------------------------------------
// K7: out[b][o][n] = x[b][o][n] + M[b][o,:] . Q[:,n] + bo[o].
// ---------------------------------------------------------------------------
__global__ __launch_bounds__(256) void k_out_t(const float* __restrict__ x,
                                               const float* __restrict__ bo,
                                               float* __restrict__ out) {
    extern __shared__ uint32_t smp[];
    uint32_t* As = smp;
    uint32_t* Bs = smp + 8192;
    const int b  = blockIdx.z;
    const int o0 = blockIdx.y * 128, n0 = blockIdx.x * 128;
    const float* Mb = g_M + (size_t)b * CDIM * CDIM;
    const float* Qf = g_qkv + (size_t)b * 2 * CDIM * NDIM;   // q plane [c][n]

    float C[2][8][4];
    #pragma unroll
    for (int mt = 0; mt < 2; mt++)
        #pragma unroll
        for (int nt = 0; nt < 8; nt++)
            #pragma unroll
            for (int r = 0; r < 4; r++) C[mt][nt][r] = 0.f;

    mma_block<8, 0, false>(Mb + (size_t)o0 * CDIM, CDIM,
                           Qf + n0, NDIM,
                           nullptr, nullptr, nullptr, 1.f, 0.f, As, Bs, C);

    const int lane = threadIdx.x & 31, wid = threadIdx.x >> 5;
    const int g = lane >> 2, t = lane & 3, wm = wid & 3, wn = wid >> 2;
    const float* xb = x   + ((size_t)b * CDIM + o0) * NDIM + n0;
    float*       ob = out + ((size_t)b * CDIM + o0) * NDIM + n0;
    #pragma unroll
    for (int mt = 0; mt < 2; mt++) {
        const int r0 = wm * 32 + mt * 16 + g;
        const float b0v = bo[o0 + r0], b1v = bo[o0 + r0 + 8];
        #pragma unroll
        for (int nt = 0; nt < 8; nt++) {
            const int col = wn * 64 + nt * 8 + 2 * t;
            float2 x0 = *(const float2*)(xb + (size_t)r0 * NDIM + col);
            float2 x1 = *(const float2*)(xb + (size_t)(r0 + 8) * NDIM + col);
            *(float2*)(ob + (size_t)r0 * NDIM + col) =
                make_float2(C[mt][nt][0] + b0v + x0.x, C[mt][nt][1] + b0v + x0.y);
            *(float2*)(ob + (size_t)(r0 + 8) * NDIM + col) =
                make_float2(C[mt][nt][2] + b1v + x1.x, C[mt][nt][3] + b1v + x1.y);
        }
    }
}

// ---------------------------------------------------------------------------
#define MMA_SMEM 65536
extern "C" void kernel_launch(void* const* d_in, const int* in_sizes, int n_in,
                              void* d_out, int out_size) {
    const float* x     = (const float*)d_in[0];
    const float* gamma = (const float*)d_in[1];
    const float* beta  = (const float*)d_in[2];
    const float* wq    = (const float*)d_in[3];
    const float* bq    = (const float*)d_in[4];
    const float* wk    = (const float*)d_in[5];
    const float* bk    = (const float*)d_in[6];
    // wv/bv folded algebraically; wo/bo used below
    const float* wv    = (const float*)d_in[7];
    const float* bv    = (const float*)d_in[8];
    const float* wo    = (const float*)d_in[9];
    const float* bo    = (const float*)d_in[10];
    float* out = (float*)d_out;

    cudaFuncSetAttribute(k_qkv_t, cudaFuncAttributeMaxDynamicSharedMemorySize, MMA_SMEM);
    cudaFuncSetAttribute(k_S,     cudaFuncAttributeMaxDynamicSharedMemorySize, MMA_SMEM);
    cudaFuncSetAttribute(k_out_t, cudaFuncAttributeMaxDynamicSharedMemorySize, MMA_SMEM);

    k_stats<<<BATCH * GRP, 256>>>(x);
    k_prep<<<dim3(4, 4), 256>>>(wo, wv, bv);
    k_qkv_t<<<dim3(NDIM / 128, 4, BATCH), 256, MMA_SMEM>>>(x, wq, bq, wk, bk, gamma, beta);
    k_S<<<dim3(2, 2, BATCH * KVSPLIT), 256, MMA_SMEM>>>(x, gamma, beta);
    k_red<<<(BATCH * CDIM * CDIM) / (256 * 4), 256>>>();
    k_M<<<dim3(4, 4, BATCH), 256>>>();
    k_out_t<<<dim3(NDIM / 128, 2, BATCH), 256, MMA_SMEM>>>(x, bo, out);
}